// round 1
// baseline (speedup 1.0000x reference)
#include <cuda_runtime.h>

#define T_STEPS 512
#define HDIM    64
#define GROUPS  4                 // batches per block
#define NTHREADS (GROUPS * HDIM)  // 256

// ---------- packed fp32x2 helpers (sm_100+ PTX) ----------
__device__ __forceinline__ unsigned long long pack2f(float lo, float hi) {
    unsigned long long r;
    asm("mov.b64 %0, {%1, %2};" : "=l"(r) : "f"(lo), "f"(hi));
    return r;
}
__device__ __forceinline__ void unpack2f(unsigned long long v, float& lo, float& hi) {
    asm("mov.b64 {%0, %1}, %2;" : "=f"(lo), "=f"(hi) : "l"(v));
}
__device__ __forceinline__ unsigned long long ffma2(unsigned long long a,
                                                    unsigned long long b,
                                                    unsigned long long c) {
    unsigned long long d;
    asm("fma.rn.f32x2 %0, %1, %2, %3;" : "=l"(d) : "l"(a), "l"(b), "l"(c));
    return d;
}
__device__ __forceinline__ unsigned long long fadd2(unsigned long long a,
                                                    unsigned long long b) {
    unsigned long long d;
    asm("add.rn.f32x2 %0, %1, %2;" : "=l"(d) : "l"(a), "l"(b));
    return d;
}
__device__ __forceinline__ unsigned smem_u32(const void* p) {
    return (unsigned)__cvta_generic_to_shared(p);
}

// One recurrence step for this thread's hidden unit.
// haddr: shared address of this group's current h[64] buffer.
__device__ __forceinline__ float rnn_step(float xv, unsigned haddr,
                                          const unsigned long long* w2,
                                          float bias, float wih) {
    unsigned long long a0 = 0ull, a1 = 0ull, a2 = 0ull, a3 = 0ull;
#pragma unroll
    for (int k = 0; k < 8; k++) {
        unsigned long long hA, hB, hC, hD;
        asm volatile("ld.shared.v2.b64 {%0,%1}, [%2];"
                     : "=l"(hA), "=l"(hB) : "r"(haddr + k * 32));
        asm volatile("ld.shared.v2.b64 {%0,%1}, [%2];"
                     : "=l"(hC), "=l"(hD) : "r"(haddr + k * 32 + 16));
        a0 = ffma2(w2[4 * k + 0], hA, a0);
        a1 = ffma2(w2[4 * k + 1], hB, a1);
        a2 = ffma2(w2[4 * k + 2], hC, a2);
        a3 = ffma2(w2[4 * k + 3], hD, a3);
    }
    unsigned long long s = fadd2(fadd2(a0, a1), fadd2(a2, a3));
    float lo, hi;
    unpack2f(s, lo, hi);
    float a = fmaf(wih, xv, bias) + lo + hi;
    // tanh(a) = 1 - 2/(e^{2a}+1): exact at +/-inf, ~1e-7 rel err via MUFU
    float e = __expf(2.0f * a);
    return 1.0f - __fdividef(2.0f, e + 1.0f);
}

__global__ __launch_bounds__(NTHREADS)
void rnn_kernel(const float* __restrict__ x,
                const float* __restrict__ W_ih,
                const float* __restrict__ W_hh,
                const float* __restrict__ b_ih,
                const float* __restrict__ b_hh,
                const float* __restrict__ fc_w,
                const float* __restrict__ fc_b,
                float* __restrict__ out) {
    __shared__ float xs[GROUPS][T_STEPS];       // staged x rows (8 KB)
    __shared__ float hbuf[2][GROUPS][HDIM];     // double-buffered hidden state
    __shared__ float red[GROUPS][HDIM];         // fc reduction scratch

    const int tid = threadIdx.x;
    const int g   = tid >> 6;        // batch group within block
    const int i   = tid & 63;        // hidden unit owned by this thread
    const int b   = blockIdx.x * GROUPS + g;

    // Stage x for the 4 batches of this block (coalesced)
    const float* xbase = x + (size_t)blockIdx.x * GROUPS * T_STEPS;
    float* xsf = &xs[0][0];
    for (int idx = tid; idx < GROUPS * T_STEPS; idx += NTHREADS)
        xsf[idx] = xbase[idx];

    // Pack this thread's W_hh row into 32 f32x2 registers
    unsigned long long w2[32];
#pragma unroll
    for (int k = 0; k < 32; k++)
        w2[k] = pack2f(W_hh[i * HDIM + 2 * k], W_hh[i * HDIM + 2 * k + 1]);

    const float bias = b_ih[i] + b_hh[i];
    const float wih  = W_ih[i];

    hbuf[0][g][i] = 0.0f;   // h0 = 0
    __syncthreads();

    const unsigned hb0 = smem_u32(&hbuf[0][g][0]);
    const unsigned hb1 = smem_u32(&hbuf[1][g][0]);

    float hcur = 0.0f;
    for (int t = 0; t < T_STEPS; t += 2) {
        hcur = rnn_step(xs[g][t], hb0, w2, bias, wih);
        hbuf[1][g][i] = hcur;
        __syncthreads();
        hcur = rnn_step(xs[g][t + 1], hb1, w2, bias, wih);
        hbuf[0][g][i] = hcur;
        __syncthreads();
    }

    // fc head on last hidden state: out[b] = sum_j hT[j]*fc_w[j] + fc_b
    red[g][i] = hcur * fc_w[i];
    __syncthreads();
    if (i == 0) {
        float s = fc_b[0];
#pragma unroll
        for (int j = 0; j < HDIM; j++) s += red[g][j];
        out[b] = s;
    }
}

extern "C" void kernel_launch(void* const* d_in, const int* in_sizes, int n_in,
                              void* d_out, int out_size) {
    const float* x    = (const float*)d_in[0];
    const float* W_ih = (const float*)d_in[1];
    const float* W_hh = (const float*)d_in[2];
    const float* b_ih = (const float*)d_in[3];
    const float* b_hh = (const float*)d_in[4];
    const float* fc_w = (const float*)d_in[5];
    const float* fc_b = (const float*)d_in[6];
    float* out = (float*)d_out;

    int B = in_sizes[0] / T_STEPS;   // I = 1
    int grid = B / GROUPS;           // 2048/4 = 512 blocks
    rnn_kernel<<<grid, NTHREADS>>>(x, W_ih, W_hh, b_ih, b_hh, fc_w, fc_b, out);
}

// round 2
// speedup vs baseline: 1.3046x; 1.3046x over previous
#include <cuda_runtime.h>

#define T_STEPS 512
#define HDIM    64
#define WPB     8                    // warps (=batches) per block
#define NTHREADS (WPB * 32)          // 256

// ---------- packed fp32x2 helpers (sm_100+ PTX) ----------
__device__ __forceinline__ unsigned long long pack2f(float lo, float hi) {
    unsigned long long r;
    asm("mov.b64 %0, {%1, %2};" : "=l"(r) : "f"(lo), "f"(hi));
    return r;
}
__device__ __forceinline__ void unpack2f(unsigned long long v, float& lo, float& hi) {
    asm("mov.b64 {%0, %1}, %2;" : "=f"(lo), "=f"(hi) : "l"(v));
}
__device__ __forceinline__ unsigned long long ffma2(unsigned long long a,
                                                    unsigned long long b,
                                                    unsigned long long c) {
    unsigned long long d;
    asm("fma.rn.f32x2 %0, %1, %2, %3;" : "=l"(d) : "l"(a), "l"(b), "l"(c));
    return d;
}
__device__ __forceinline__ unsigned long long fadd2(unsigned long long a,
                                                    unsigned long long b) {
    unsigned long long d;
    asm("add.rn.f32x2 %0, %1, %2;" : "=l"(d) : "l"(a), "l"(b));
    return d;
}
__device__ __forceinline__ unsigned smem_u32(const void* p) {
    return (unsigned)__cvta_generic_to_shared(p);
}
__device__ __forceinline__ float fast_tanh(float a) {
    // tanh(a) = 1 - 2/(e^{2a}+1); exact at +/-inf, ~1e-7 rel err via MUFU
    float e = __expf(2.0f * a);
    return 1.0f - __fdividef(2.0f, e + 1.0f);
}

// One recurrence step for the 2 rows owned by this lane. Warp-synchronous.
// haddr: shared addr of this warp's current h[64] buffer.
__device__ __forceinline__ void rnn_step2(float xv, unsigned haddr,
                                          const unsigned long long* w0,
                                          const unsigned long long* w1,
                                          float b0, float b1,
                                          float wi0, float wi1,
                                          float& h0, float& h1) {
    unsigned long long a0 = 0ull, a1 = 0ull, a2 = 0ull, a3 = 0ull;
#pragma unroll
    for (int k = 0; k < 16; k++) {
        unsigned long long hA, hB;      // h pairs (4 floats), broadcast across warp
        asm volatile("ld.shared.v2.b64 {%0,%1}, [%2];"
                     : "=l"(hA), "=l"(hB) : "r"(haddr + k * 16));
        a0 = ffma2(w0[2 * k    ], hA, a0);
        a1 = ffma2(w0[2 * k + 1], hB, a1);
        a2 = ffma2(w1[2 * k    ], hA, a2);
        a3 = ffma2(w1[2 * k + 1], hB, a3);
    }
    unsigned long long s0 = fadd2(a0, a1);
    unsigned long long s1 = fadd2(a2, a3);
    float l0, u0, l1, u1;
    unpack2f(s0, l0, u0);
    unpack2f(s1, l1, u1);
    h0 = fast_tanh(fmaf(wi0, xv, b0) + l0 + u0);
    h1 = fast_tanh(fmaf(wi1, xv, b1) + l1 + u1);
}

__global__ __launch_bounds__(NTHREADS, 1)
void rnn_kernel(const float* __restrict__ x,
                const float* __restrict__ W_ih,
                const float* __restrict__ W_hh,
                const float* __restrict__ b_ih,
                const float* __restrict__ b_hh,
                const float* __restrict__ fc_w,
                const float* __restrict__ fc_b,
                float* __restrict__ out) {
    __shared__ float xs[WPB][T_STEPS];        // staged x rows (16 KB)
    __shared__ float hbuf[2][WPB][HDIM];      // double-buffered hidden state (4 KB)

    const int tid  = threadIdx.x;
    const int w    = tid >> 5;                // warp = batch within block
    const int lane = tid & 31;
    const int r0   = 2 * lane;                // rows owned by this lane
    const int b    = blockIdx.x * WPB + w;

    // Stage x for the WPB batches of this block (coalesced)
    const float* xbase = x + (size_t)blockIdx.x * WPB * T_STEPS;
    float* xsf = &xs[0][0];
    for (int idx = tid; idx < WPB * T_STEPS; idx += NTHREADS)
        xsf[idx] = xbase[idx];

    // Pack both W_hh rows into 64 f32x2 registers (weights shared by all batches)
    unsigned long long w0r[32], w1r[32];
#pragma unroll
    for (int j = 0; j < 16; j++) {
        float4 v0 = __ldg((const float4*)(W_hh + (size_t)r0 * HDIM       + 4 * j));
        float4 v1 = __ldg((const float4*)(W_hh + (size_t)(r0 + 1) * HDIM + 4 * j));
        w0r[2 * j]     = pack2f(v0.x, v0.y);
        w0r[2 * j + 1] = pack2f(v0.z, v0.w);
        w1r[2 * j]     = pack2f(v1.x, v1.y);
        w1r[2 * j + 1] = pack2f(v1.z, v1.w);
    }
    const float bias0 = b_ih[r0]     + b_hh[r0];
    const float bias1 = b_ih[r0 + 1] + b_hh[r0 + 1];
    const float wi0   = W_ih[r0];
    const float wi1   = W_ih[r0 + 1];
    const float fw0   = fc_w[r0];
    const float fw1   = fc_w[r0 + 1];

    // h0 = 0
    hbuf[0][w][r0]     = 0.0f;
    hbuf[0][w][r0 + 1] = 0.0f;
    __syncthreads();   // covers x staging + h init; only block-wide sync

    const unsigned hb0 = smem_u32(&hbuf[0][w][0]);
    const unsigned hb1 = smem_u32(&hbuf[1][w][0]);
    const unsigned hst0 = hb0 + 8 * lane;     // this lane's f32x2 slot
    const unsigned hst1 = hb1 + 8 * lane;

    float h0 = 0.0f, h1 = 0.0f;
    for (int t = 0; t < T_STEPS; t += 2) {
        rnn_step2(xs[w][t], hb0, w0r, w1r, bias0, bias1, wi0, wi1, h0, h1);
        asm volatile("st.shared.v2.f32 [%0], {%1,%2};" :: "r"(hst1), "f"(h0), "f"(h1));
        __syncwarp();
        rnn_step2(xs[w][t + 1], hb1, w0r, w1r, bias0, bias1, wi0, wi1, h0, h1);
        asm volatile("st.shared.v2.f32 [%0], {%1,%2};" :: "r"(hst0), "f"(h0), "f"(h1));
        __syncwarp();
    }

    // fc head: out[b] = sum_j hT[j]*fc_w[j] + fc_b   (warp butterfly reduce)
    float v = h0 * fw0 + h1 * fw1;
#pragma unroll
    for (int off = 16; off > 0; off >>= 1)
        v += __shfl_xor_sync(0xFFFFFFFFu, v, off);
    if (lane == 0) out[b] = v + fc_b[0];
}

extern "C" void kernel_launch(void* const* d_in, const int* in_sizes, int n_in,
                              void* d_out, int out_size) {
    const float* x    = (const float*)d_in[0];
    const float* W_ih = (const float*)d_in[1];
    const float* W_hh = (const float*)d_in[2];
    const float* b_ih = (const float*)d_in[3];
    const float* b_hh = (const float*)d_in[4];
    const float* fc_w = (const float*)d_in[5];
    const float* fc_b = (const float*)d_in[6];
    float* out = (float*)d_out;

    int B = in_sizes[0] / T_STEPS;     // I = 1
    int grid = B / WPB;                // 2048/8 = 256 blocks
    rnn_kernel<<<grid, NTHREADS>>>(x, W_ih, W_hh, b_ih, b_hh, fc_w, fc_b, out);
}

// round 4
// speedup vs baseline: 1.4903x; 1.1423x over previous
#include <cuda_runtime.h>

#define T_STEPS 512
#define HDIM    64
#define WPB     8                    // warps per block
#define BPW     2                    // batches per warp
#define BPB     (WPB * BPW)          // 16 batches per block
#define NTHREADS (WPB * 32)          // 256

// ---------- packed fp32x2 helpers (sm_100+ PTX) ----------
__device__ __forceinline__ unsigned long long pack2f(float lo, float hi) {
    unsigned long long r;
    asm("mov.b64 %0, {%1, %2};" : "=l"(r) : "f"(lo), "f"(hi));
    return r;
}
__device__ __forceinline__ void unpack2f(unsigned long long v, float& lo, float& hi) {
    asm("mov.b64 {%0, %1}, %2;" : "=f"(lo), "=f"(hi) : "l"(v));
}
__device__ __forceinline__ unsigned long long ffma2(unsigned long long a,
                                                    unsigned long long b,
                                                    unsigned long long c) {
    unsigned long long d;
    asm("fma.rn.f32x2 %0, %1, %2, %3;" : "=l"(d) : "l"(a), "l"(b), "l"(c));
    return d;
}
__device__ __forceinline__ unsigned long long fadd2(unsigned long long a,
                                                    unsigned long long b) {
    unsigned long long d;
    asm("add.rn.f32x2 %0, %1, %2;" : "=l"(d) : "l"(a), "l"(b));
    return d;
}
__device__ __forceinline__ unsigned smem_u32(const void* p) {
    return (unsigned)__cvta_generic_to_shared(p);
}
__device__ __forceinline__ float fast_tanh(float a) {
    // tanh(a) = 1 - 2/(e^{2a}+1); exact at +/-inf, ~1e-7 rel err via MUFU
    float e = __expf(2.0f * a);
    return 1.0f - __fdividef(2.0f, e + 1.0f);
}

// One recurrence step for 2 rows x 2 batches. Warp-synchronous.
__device__ __forceinline__ void rnn_step22(float xA, float xB,
                                           unsigned haddrA, unsigned haddrB,
                                           const unsigned long long* w0,
                                           const unsigned long long* w1,
                                           float b0, float b1,
                                           float wi0, float wi1,
                                           float& hA0, float& hA1,
                                           float& hB0, float& hB1) {
    unsigned long long aA0 = 0ull, aA1 = 0ull, aA2 = 0ull, aA3 = 0ull;
    unsigned long long aB0 = 0ull, aB1 = 0ull, aB2 = 0ull, aB3 = 0ull;
#pragma unroll
    for (int k = 0; k < 16; k++) {
        unsigned long long pA0, pA1, pB0, pB1;   // broadcast h pairs
        asm volatile("ld.shared.v2.b64 {%0,%1}, [%2];"
                     : "=l"(pA0), "=l"(pA1) : "r"(haddrA + k * 16));
        asm volatile("ld.shared.v2.b64 {%0,%1}, [%2];"
                     : "=l"(pB0), "=l"(pB1) : "r"(haddrB + k * 16));
        aA0 = ffma2(w0[2 * k    ], pA0, aA0);
        aA1 = ffma2(w0[2 * k + 1], pA1, aA1);
        aA2 = ffma2(w1[2 * k    ], pA0, aA2);
        aA3 = ffma2(w1[2 * k + 1], pA1, aA3);
        aB0 = ffma2(w0[2 * k    ], pB0, aB0);
        aB1 = ffma2(w0[2 * k + 1], pB1, aB1);
        aB2 = ffma2(w1[2 * k    ], pB0, aB2);
        aB3 = ffma2(w1[2 * k + 1], pB1, aB3);
    }
    float l, u;
    unsigned long long sA0 = fadd2(aA0, aA1);
    unsigned long long sA1 = fadd2(aA2, aA3);
    unsigned long long sB0 = fadd2(aB0, aB1);
    unsigned long long sB1 = fadd2(aB2, aB3);
    unpack2f(sA0, l, u); hA0 = fast_tanh(fmaf(wi0, xA, b0) + l + u);
    unpack2f(sA1, l, u); hA1 = fast_tanh(fmaf(wi1, xA, b1) + l + u);
    unpack2f(sB0, l, u); hB0 = fast_tanh(fmaf(wi0, xB, b0) + l + u);
    unpack2f(sB1, l, u); hB1 = fast_tanh(fmaf(wi1, xB, b1) + l + u);
}

__global__ __launch_bounds__(NTHREADS, 1)
void rnn_kernel(const float* __restrict__ x,
                const float* __restrict__ W_ih,
                const float* __restrict__ W_hh,
                const float* __restrict__ b_ih,
                const float* __restrict__ b_hh,
                const float* __restrict__ fc_w,
                const float* __restrict__ fc_b,
                float* __restrict__ out) {
    __shared__ float xs[BPB][T_STEPS];        // staged x rows (32 KB)
    __shared__ float hbuf[2][BPB][HDIM];      // double-buffered hidden state (8 KB)

    const int tid  = threadIdx.x;
    const int w    = tid >> 5;                // warp index
    const int lane = tid & 31;
    const int r0   = 2 * lane;                // rows owned by this lane
    const int gA   = 2 * w;                   // batch slots within block
    const int gB   = 2 * w + 1;
    const int bA   = blockIdx.x * BPB + gA;
    const int bB   = blockIdx.x * BPB + gB;

    // Stage x for the 16 batches of this block (coalesced float4)
    {
        const float4* src = (const float4*)(x + (size_t)blockIdx.x * BPB * T_STEPS);
        float4* dst = (float4*)&xs[0][0];
#pragma unroll
        for (int idx = tid; idx < BPB * T_STEPS / 4; idx += NTHREADS)
            dst[idx] = src[idx];
    }

    // Pack both W_hh rows into 64 f32x2 registers (shared across both batches)
    unsigned long long w0r[32], w1r[32];
#pragma unroll
    for (int j = 0; j < 16; j++) {
        float4 v0 = __ldg((const float4*)(W_hh + (size_t)r0 * HDIM       + 4 * j));
        float4 v1 = __ldg((const float4*)(W_hh + (size_t)(r0 + 1) * HDIM + 4 * j));
        w0r[2 * j]     = pack2f(v0.x, v0.y);
        w0r[2 * j + 1] = pack2f(v0.z, v0.w);
        w1r[2 * j]     = pack2f(v1.x, v1.y);
        w1r[2 * j + 1] = pack2f(v1.z, v1.w);
    }
    const float bias0 = b_ih[r0]     + b_hh[r0];
    const float bias1 = b_ih[r0 + 1] + b_hh[r0 + 1];
    const float wi0   = W_ih[r0];
    const float wi1   = W_ih[r0 + 1];
    const float fw0   = fc_w[r0];
    const float fw1   = fc_w[r0 + 1];

    // h0 = 0 for both batches
    hbuf[0][gA][r0] = 0.0f; hbuf[0][gA][r0 + 1] = 0.0f;
    hbuf[0][gB][r0] = 0.0f; hbuf[0][gB][r0 + 1] = 0.0f;
    __syncthreads();   // covers x staging + h init; only block-wide sync

    const unsigned hA0b = smem_u32(&hbuf[0][gA][0]);
    const unsigned hA1b = smem_u32(&hbuf[1][gA][0]);
    const unsigned hB0b = smem_u32(&hbuf[0][gB][0]);
    const unsigned hB1b = smem_u32(&hbuf[1][gB][0]);
    const unsigned stA0 = hA0b + 8 * lane;    // this lane's f32x2 slots
    const unsigned stA1 = hA1b + 8 * lane;
    const unsigned stB0 = hB0b + 8 * lane;
    const unsigned stB1 = hB1b + 8 * lane;

    float hA0 = 0.f, hA1 = 0.f, hB0 = 0.f, hB1 = 0.f;
    for (int t = 0; t < T_STEPS; t += 2) {
        rnn_step22(xs[gA][t], xs[gB][t], hA0b, hB0b, w0r, w1r,
                   bias0, bias1, wi0, wi1, hA0, hA1, hB0, hB1);
        asm volatile("st.shared.v2.f32 [%0], {%1,%2};" :: "r"(stA1), "f"(hA0), "f"(hA1));
        asm volatile("st.shared.v2.f32 [%0], {%1,%2};" :: "r"(stB1), "f"(hB0), "f"(hB1));
        __syncwarp();
        rnn_step22(xs[gA][t + 1], xs[gB][t + 1], hA1b, hB1b, w0r, w1r,
                   bias0, bias1, wi0, wi1, hA0, hA1, hB0, hB1);
        asm volatile("st.shared.v2.f32 [%0], {%1,%2};" :: "r"(stA0), "f"(hA0), "f"(hA1));
        asm volatile("st.shared.v2.f32 [%0], {%1,%2};" :: "r"(stB0), "f"(hB0), "f"(hB1));
        __syncwarp();
    }

    // fc head per batch: out[b] = sum_j hT[j]*fc_w[j] + fc_b   (warp butterfly)
    float vA = hA0 * fw0 + hA1 * fw1;
    float vB = hB0 * fw0 + hB1 * fw1;
#pragma unroll
    for (int off = 16; off > 0; off >>= 1) {
        vA += __shfl_xor_sync(0xFFFFFFFFu, vA, off);
        vB += __shfl_xor_sync(0xFFFFFFFFu, vB, off);
    }
    if (lane == 0) { out[bA] = vA + fc_b[0]; out[bB] = vB + fc_b[0]; }
}

extern "C" void kernel_launch(void* const* d_in, const int* in_sizes, int n_in,
                              void* d_out, int out_size) {
    const float* x    = (const float*)d_in[0];
    const float* W_ih = (const float*)d_in[1];
    const float* W_hh = (const float*)d_in[2];
    const float* b_ih = (const float*)d_in[3];
    const float* b_hh = (const float*)d_in[4];
    const float* fc_w = (const float*)d_in[5];
    const float* fc_b = (const float*)d_in[6];
    float* out = (float*)d_out;

    int B = in_sizes[0] / T_STEPS;     // I = 1
    int grid = B / BPB;                // 2048/16 = 128 blocks — single wave
    rnn_kernel<<<grid, NTHREADS>>>(x, W_ih, W_hh, b_ih, b_hh, fc_w, fc_b, out);
}